// round 11
// baseline (speedup 1.0000x reference)
#include <cuda_runtime.h>
#include <cuda_fp16.h>
#include <cstdint>

// ---------------- problem constants ----------------
#define N_ROWS 16384
#define KC 8192
#define D 256
#define LOSS_OFF 4194304
#define IDX_OFF 4194305
#define QCAP (1 << 20)

typedef unsigned long long u64;

// ---------------- device scratch ----------------
__device__ __half g_Ah[(size_t)N_ROWS * D];   // x fp16 [m][k]
__device__ __half g_Bh[(size_t)KC * D];       // e fp16 [n][k]
__device__ float g_Axf[(size_t)N_ROWS * D];   // x fp32 row-major (exact recheck)
__device__ float g_en2[KC];                   // ||e||^2 fp32
__device__ float g_xn2[N_ROWS];               // ||x||^2 per row
__device__ int g_maxen = 0;                   // max ||e||^2 bits (atomicMax, idempotent)
__device__ u64 g_part[(size_t)N_ROWS * 64];   // per row: 32 blocks(256) x top-2
__device__ int g_idx[N_ROWS];
__device__ u64 g_best[N_ROWS];                // packed best for queued rows
__device__ int g_queue[QCAP];                 // candidate tasks: (row<<13)|k
__device__ int g_rowq[N_ROWS];                // queued rows
__device__ int g_qn;                          // task count
__device__ int g_rqn;                         // row count

// ---------------- helpers ----------------
__device__ __forceinline__ uint32_t smem_u32(const void* p) {
    uint32_t a;
    asm("{ .reg .u64 t; cvta.to.shared.u64 t, %1; cvt.u32.u64 %0, t; }" : "=r"(a) : "l"(p));
    return a;
}
__device__ __forceinline__ u64 packdi(float d, int idx) {
    uint32_t u = __float_as_uint(d);
    u = (u & 0x80000000u) ? ~u : (u | 0x80000000u);
    return ((u64)u << 32) | (uint32_t)idx;
}
__device__ __forceinline__ float unpackd(u64 p) {
    uint32_t u = (uint32_t)(p >> 32);
    u = (u & 0x80000000u) ? (u ^ 0x80000000u) : ~u;
    return __uint_as_float(u);
}
__device__ __forceinline__ void cpasync16(uint32_t sdst, const void* gsrc) {
    asm volatile("cp.async.cg.shared.global [%0], [%1], 16;" :: "r"(sdst), "l"(gsrc));
}
__device__ __forceinline__ void ldmx4(uint32_t addr, uint32_t& r0, uint32_t& r1,
                                      uint32_t& r2, uint32_t& r3) {
    asm volatile("ldmatrix.sync.aligned.m8n8.x4.shared.b16 {%0,%1,%2,%3}, [%4];"
                 : "=r"(r0), "=r"(r1), "=r"(r2), "=r"(r3) : "r"(addr));
}
// fp16-accumulate MMA: D(f16x2 x2) = A*B + D
__device__ __forceinline__ void mma16816h(uint32_t* c, const uint32_t* a, const uint32_t* b) {
    asm volatile(
        "mma.sync.aligned.m16n8k16.row.col.f16.f16.f16.f16 "
        "{%0,%1}, {%2,%3,%4,%5}, {%6,%7}, {%0,%1};"
        : "+r"(c[0]), "+r"(c[1])
        : "r"(a[0]), "r"(a[1]), "r"(a[2]), "r"(a[3]), "r"(b[0]), "r"(b[1]));
}

// ---------------- prepE: E -> fp16 + ||e||^2 + max norm + inits --------------------
__global__ void prepE_kernel(const float* __restrict__ E, float* out) {
    int k = blockIdx.x * 8 + (threadIdx.x >> 5);
    int lane = threadIdx.x & 31;
    if (blockIdx.x == 0 && threadIdx.x == 0) { out[LOSS_OFF] = 0.0f; g_qn = 0; g_rqn = 0; }
    const float4* p = (const float4*)(E + (size_t)k * D);
    float4 v0 = p[lane * 2], v1 = p[lane * 2 + 1];
    __half2 h0 = __floats2half2_rn(v0.x, v0.y), h1 = __floats2half2_rn(v0.z, v0.w);
    __half2 h2 = __floats2half2_rn(v1.x, v1.y), h3 = __floats2half2_rn(v1.z, v1.w);
    uint4 o;
    o.x = *(uint32_t*)&h0; o.y = *(uint32_t*)&h1;
    o.z = *(uint32_t*)&h2; o.w = *(uint32_t*)&h3;
    *(uint4*)(g_Bh + (size_t)k * D + lane * 8) = o;
    float s = v0.x*v0.x + v0.y*v0.y + v0.z*v0.z + v0.w*v0.w
            + v1.x*v1.x + v1.y*v1.y + v1.z*v1.z + v1.w*v1.w;
    #pragma unroll
    for (int off = 16; off > 0; off >>= 1) s += __shfl_xor_sync(0xffffffffu, s, off);
    if (lane == 0) {
        g_en2[k] = s;
        atomicMax(&g_maxen, __float_as_int(s));
    }
}

// ---------------- prepA: hs -> g_Ah fp16 + g_Axf fp32 (transposed), row norms ------
__global__ void prepA_kernel(const float* __restrict__ hs) {
    __shared__ float tile[32][33];
    __shared__ float snorm[8][32];
    int m0 = blockIdx.x * 32, b = m0 >> 10, p0 = m0 & 1023;
    int tx = threadIdx.x, ty = threadIdx.y;   // 32 x 8
    float nacc = 0.0f;
    for (int cc = 0; cc < 8; cc++) {
        int c0 = cc * 32;
        __syncthreads();
        #pragma unroll
        for (int i = 0; i < 4; i++) {
            int c = c0 + ty + i * 8;
            float v = hs[((size_t)(b * 256 + c)) * 1024 + p0 + tx];
            tile[ty + i * 8][tx] = v;
            nacc = fmaf(v, v, nacc);
        }
        __syncthreads();
        #pragma unroll
        for (int i = 0; i < 4; i++) {
            int row = ty + i * 8;
            float v = tile[tx][row];
            g_Ah[(size_t)(m0 + row) * D + c0 + tx] = __float2half_rn(v);
            g_Axf[(size_t)(m0 + row) * D + c0 + tx] = v;
        }
    }
    snorm[ty][tx] = nacc;
    __syncthreads();
    if (ty == 0) {
        float tot = 0.0f;
        #pragma unroll
        for (int j = 0; j < 8; j++) tot += snorm[j][tx];
        g_xn2[m0 + tx] = tot;
    }
}

// ---------------- main GEMM: CTA 128x256, 8 warps of 64x64, fp16 accum -------------
#define SA_OFF(b) ((b) * 16384)
#define SB_OFF(b) (32768 + (b) * 32768)
#define SEN_OFF   98304
#define SPART_OFF 99328
#define SMEM_SZ   (1024 + 99328 + 8192)

__global__ void __launch_bounds__(256, 2)
gemm_kernel() {
    extern __shared__ char smem_raw[];
    char* base = (char*)(((uintptr_t)smem_raw + 1023) & ~(uintptr_t)1023);
    uint32_t sb = smem_u32(base);
    float* sEn = (float*)(base + SEN_OFF);
    u64* sPart = (u64*)(base + SPART_OFF);

    const int tid = threadIdx.x;
    const int lane = tid & 31, wid = tid >> 5;
    const int wm = wid & 1, wn = wid >> 1;          // 2M x 4N warps, 64x64 tiles
    const int ntile = blockIdx.x, mtile = blockIdx.y;
    const int m0 = mtile * 128, n0 = ntile * 256;

    if (tid < 256) sEn[tid] = g_en2[n0 + tid];

    auto load_chunk = [&](int c, int bf) {
        #pragma unroll
        for (int it = 0; it < 4; it++) {              // A: 1024 x 16B
            int idx = tid + it * 256;
            int row = idx >> 3, kg = idx & 7;
            uint32_t soff = row * 128 + (((uint32_t)(kg ^ (row & 7))) << 4);
            cpasync16(sb + SA_OFF(bf) + soff,
                      g_Ah + (size_t)(m0 + row) * D + c * 64 + kg * 8);
        }
        #pragma unroll
        for (int it = 0; it < 8; it++) {              // B: 2048 x 16B
            int idx = tid + it * 256;
            int row = idx >> 3, kg = idx & 7;
            uint32_t soff = row * 128 + (((uint32_t)(kg ^ (row & 7))) << 4);
            cpasync16(sb + SB_OFF(bf) + soff,
                      g_Bh + (size_t)(n0 + row) * D + c * 64 + kg * 8);
        }
        asm volatile("cp.async.commit_group;");
    };

    uint32_t acc[4][8][2];                            // fp16x2 accumulators
    #pragma unroll
    for (int mt = 0; mt < 4; mt++)
        #pragma unroll
        for (int nt = 0; nt < 8; nt++)
            acc[mt][nt][0] = acc[mt][nt][1] = 0u;

    load_chunk(0, 0);

    for (int c = 0; c < 4; c++) {
        if (c + 1 < 4) {
            load_chunk(c + 1, (c + 1) & 1);
            asm volatile("cp.async.wait_group 1;" ::: "memory");
        } else {
            asm volatile("cp.async.wait_group 0;" ::: "memory");
        }
        __syncthreads();
        uint32_t ab = sb + SA_OFF(c & 1), bbse = sb + SB_OFF(c & 1);
        #pragma unroll
        for (int ks = 0; ks < 4; ks++) {
            uint32_t a[4][4], bb[8][2];
            uint32_t kg = ks * 2 + (lane >> 4);
            uint32_t kx = ((kg ^ (lane & 7)) << 4);
            #pragma unroll
            for (int mt = 0; mt < 4; mt++) {
                uint32_t row = wm * 64 + mt * 16 + (lane & 15);
                ldmx4(ab + row * 128 + kx, a[mt][0], a[mt][1], a[mt][2], a[mt][3]);
            }
            #pragma unroll
            for (int nt2 = 0; nt2 < 4; nt2++) {
                uint32_t row = wn * 64 + nt2 * 16 + (lane & 15);
                uint32_t r0, r1, r2, r3;
                ldmx4(bbse + row * 128 + kx, r0, r1, r2, r3);
                bb[nt2 * 2][0] = r0; bb[nt2 * 2][1] = r2;
                bb[nt2 * 2 + 1][0] = r1; bb[nt2 * 2 + 1][1] = r3;
            }
            #pragma unroll
            for (int mt = 0; mt < 4; mt++)
                #pragma unroll
                for (int nt = 0; nt < 8; nt++)
                    mma16816h(acc[mt][nt], a[mt], bb[nt]);
        }
        __syncthreads();
    }

    // epilogue: per-row top-2 of dist = en2 - 2*dot within this warp's 64-col strip
    #pragma unroll
    for (int mt = 0; mt < 4; mt++) {
        #pragma unroll
        for (int half = 0; half < 2; half++) {
            u64 t1 = ~0ull, t2 = ~0ull;
            #pragma unroll
            for (int nt = 0; nt < 8; nt++) {
                __half2 hv = *(__half2*)&acc[mt][nt][half];
                float2 fv = __half22float2(hv);
                int col = wn * 64 + nt * 8 + (lane & 3) * 2;
                float d0 = fmaf(-2.0f, fv.x, sEn[col]);
                float d1 = fmaf(-2.0f, fv.y, sEn[col + 1]);
                u64 p0 = packdi(d0, n0 + col);
                u64 p1 = packdi(d1, n0 + col + 1);
                if (p0 < t1) { t2 = t1; t1 = p0; } else if (p0 < t2) t2 = p0;
                if (p1 < t1) { t2 = t1; t1 = p1; } else if (p1 < t2) t2 = p1;
            }
            #pragma unroll
            for (int dlt = 1; dlt <= 2; dlt <<= 1) {
                u64 o1 = __shfl_xor_sync(0xffffffffu, t1, dlt);
                u64 o2 = __shfl_xor_sync(0xffffffffu, t2, dlt);
                u64 n1 = min(t1, o1);
                u64 n2 = min(max(t1, o1), min(t2, o2));
                t1 = n1; t2 = n2;
            }
            if ((lane & 3) == 0) {
                int rl = wm * 64 + mt * 16 + half * 8 + (lane >> 2);
                sPart[rl * 8 + wn * 2] = t1;
                sPart[rl * 8 + wn * 2 + 1] = t2;
            }
        }
    }
    __syncthreads();
    if (tid < 128) {
        u64 p1 = ~0ull, p2 = ~0ull;
        #pragma unroll
        for (int w = 0; w < 4; w++) {
            u64 a1 = sPart[tid * 8 + w * 2], a2 = sPart[tid * 8 + w * 2 + 1];
            u64 n1 = min(p1, a1);
            u64 n2 = min(max(p1, a1), min(p2, a2));
            p1 = n1; p2 = n2;
        }
        g_part[(size_t)(m0 + tid) * 64 + ntile * 2] = p1;
        g_part[(size_t)(m0 + tid) * 64 + ntile * 2 + 1] = p2;
    }
}

// ---------------- merge_fast: warp/row, fast path or enqueue candidate tasks --------
__global__ void merge_fast_kernel(float* __restrict__ out) {
    int wid = threadIdx.x >> 5, lane = threadIdx.x & 31;
    int row = blockIdx.x * 8 + wid;

    const ulonglong2* pp = (const ulonglong2*)(g_part + (size_t)row * 64);
    ulonglong2 ea = pp[lane];                  // block 'lane' (256 codes): top1, top2

    u64 m = min(ea.x, ea.y);
    #pragma unroll
    for (int o = 16; o > 0; o >>= 1) m = min(m, __shfl_xor_sync(0xffffffffu, m, o));

    // pad covers fp16 inputs (2^-10) + fp16 accumulation (~16 roundings); empirical
    // error is ~60x smaller than this bound.
    float pad = 0.011f * sqrtf(__ldg(&g_xn2[row]) * __int_as_float(g_maxen)) + 0.1f;
    float thr = unpackd(m) + pad;

    bool f = unpackd(ea.y) <= thr;             // whole 256-block recheck
    bool cnd = (!f) && (unpackd(ea.x) <= thr);
    unsigned mf = __ballot_sync(0xffffffffu, f);
    int nc = __popc(__ballot_sync(0xffffffffu, cnd));

    if (mf == 0 && nc == 1) {
        if (lane == 0) {
            int k = (int)(m & 0xFFFFFFFFu);
            g_idx[row] = k;
            out[IDX_OFF + row] = (float)k;
        }
        return;
    }

    if (lane == 0) {
        g_best[row] = ~0ull;
        g_rowq[atomicAdd(&g_rqn, 1)] = row;
    }
    int rsh = row << 13;
    if (cnd) {
        int q = atomicAdd(&g_qn, 1);
        if (q < QCAP) g_queue[q] = rsh | (int)(ea.x & 0x1FFFu);
    }
    if (f) {
        int q = atomicAdd(&g_qn, 256);
        int k0 = lane * 256;
        for (int i = 0; i < 256 && q + i < QCAP; i++) g_queue[q + i] = rsh | (k0 + i);
    }
}

// ---------------- merge_slow: one warp per candidate task ---------------------------
__global__ void __launch_bounds__(256, 8)
merge_slow_kernel(const float* __restrict__ E) {
    int nt = g_qn;
    if (nt > QCAP) nt = QCAP;
    int lane = threadIdx.x & 31;
    int gw = (blockIdx.x * 256 + threadIdx.x) >> 5;
    int nwarp = (gridDim.x * 256) >> 5;

    for (int t = gw; t < nt; t += nwarp) {
        int task = g_queue[t];
        int row = task >> 13, k = task & 0x1FFF;
        const float* xr = g_Axf + (size_t)row * D;
        const float* ek = E + (size_t)k * D;
        float s = 0.0f;
        #pragma unroll
        for (int j = 0; j < 8; j++)
            s = fmaf(__ldg(xr + lane + j * 32), __ldg(ek + lane + j * 32), s);
        #pragma unroll
        for (int o = 16; o > 0; o >>= 1) s += __shfl_xor_sync(0xffffffffu, s, o);
        if (lane == 0) {
            float dist = fmaf(-2.0f, s, __ldg(&g_en2[k]));
            atomicMin(&g_best[row], packdi(dist, k));
        }
    }
}

// ---------------- merge_fin: finalize queued rows ------------------------------------
__global__ void merge_fin_kernel(float* __restrict__ out) {
    int n = g_rqn;
    for (int i = blockIdx.x * 256 + threadIdx.x; i < n; i += gridDim.x * 256) {
        int row = g_rowq[i];
        int k = (int)(g_best[row] & 0xFFFFFFFFu);
        g_idx[row] = k;
        out[IDX_OFF + row] = (float)k;
    }
}

// ---------------- final gather + loss (float4) --------------------------------------
__global__ void final_kernel(const float* __restrict__ hs,
                             const float* __restrict__ E,
                             float* __restrict__ out) {
    __shared__ int sIdx[128];
    __shared__ float sRed[8];
    int tid = threadIdx.x;
    int lane = tid & 31;
    int row0 = blockIdx.x * 128;
    int b = row0 >> 10, p0 = row0 & 1023;
    size_t xbase = (size_t)b * 256 * 1024 + p0;

    if (tid < 128) sIdx[tid] = g_idx[row0 + tid];
    __syncthreads();

    int k0 = sIdx[lane * 4], k1 = sIdx[lane * 4 + 1];
    int k2 = sIdx[lane * 4 + 2], k3 = sIdx[lane * 4 + 3];

    float lsum = 0.0f;
    #pragma unroll 4
    for (int i = 0; i < 32; i++) {
        int c = i * 8 + (tid >> 5);
        size_t ad = xbase + (size_t)c * 1024 + lane * 4;
        float4 xv = *(const float4*)(hs + ad);
        float4 ev;
        ev.x = __ldg(E + (size_t)k0 * D + c);
        ev.y = __ldg(E + (size_t)k1 * D + c);
        ev.z = __ldg(E + (size_t)k2 * D + c);
        ev.w = __ldg(E + (size_t)k3 * D + c);
        *(float4*)(out + ad) = ev;
        float d0 = ev.x - xv.x, d1 = ev.y - xv.y;
        float d2 = ev.z - xv.z, d3 = ev.w - xv.w;
        lsum = fmaf(d0, d0, lsum);
        lsum = fmaf(d1, d1, lsum);
        lsum = fmaf(d2, d2, lsum);
        lsum = fmaf(d3, d3, lsum);
    }
    #pragma unroll
    for (int o = 16; o > 0; o >>= 1) lsum += __shfl_xor_sync(0xffffffffu, lsum, o);
    if ((tid & 31) == 0) sRed[tid >> 5] = lsum;
    __syncthreads();
    if (tid == 0) {
        float tot = 0.0f;
        #pragma unroll
        for (int w = 0; w < 8; w++) tot += sRed[w];
        atomicAdd(out + LOSS_OFF, tot * (1.25f / 4194304.0f));
    }
}

extern "C" void kernel_launch(void* const* d_in, const int* in_sizes, int n_in,
                              void* d_out, int out_size) {
    const float* hs = (const float*)d_in[0];
    const float* E  = (const float*)d_in[1];
    float* out = (float*)d_out;

    cudaFuncSetAttribute(gemm_kernel,
                         cudaFuncAttributeMaxDynamicSharedMemorySize, SMEM_SZ);

    prepE_kernel<<<KC / 8, 256>>>(E, out);
    prepA_kernel<<<N_ROWS / 32, dim3(32, 8)>>>(hs);
    gemm_kernel<<<dim3(KC / 256, N_ROWS / 128), 256, SMEM_SZ>>>();
    merge_fast_kernel<<<N_ROWS / 8, 256>>>(out);
    merge_slow_kernel<<<592, 256>>>(E);
    merge_fin_kernel<<<32, 256>>>(out);
    final_kernel<<<N_ROWS / 128, 256>>>(hs, E, out);
}

// round 13
// speedup vs baseline: 1.0796x; 1.0796x over previous
#include <cuda_runtime.h>
#include <cuda_fp16.h>
#include <cstdint>

// ---------------- problem constants ----------------
#define N_ROWS 16384
#define KC 8192
#define D 256
#define LOSS_OFF 4194304
#define IDX_OFF 4194305
#define QCAP (1 << 20)

typedef unsigned long long u64;

// ---------------- device scratch ----------------
__device__ __half g_Ah[(size_t)N_ROWS * D];   // x fp16 [m][k]
__device__ __half g_Bh[(size_t)KC * D];       // e fp16 [n][k]
__device__ float g_Axf[(size_t)N_ROWS * D];   // x fp32 row-major (exact recheck)
__device__ float g_en2[KC];                   // ||e||^2 fp32
__device__ float g_xn2[N_ROWS];               // ||x||^2 per row
__device__ int g_maxen = 0;                   // max ||e||^2 bits (atomicMax, idempotent)
__device__ u64 g_part[(size_t)N_ROWS * 64];   // per row/tile: [d1|idx13|dq19] packed
__device__ int g_idx[N_ROWS];                 // fast-path idx, or -1 -> use g_best
__device__ u64 g_best[N_ROWS];                // packed best for queued rows
__device__ int g_queue[QCAP];                 // candidate tasks: (row<<13)|k
__device__ int g_qn;                          // task count
__device__ int g_cnt[128];                    // per-mtile completion counters

// ---------------- helpers ----------------
__device__ __forceinline__ uint32_t smem_u32(const void* p) {
    uint32_t a;
    asm("{ .reg .u64 t; cvta.to.shared.u64 t, %1; cvt.u32.u64 %0, t; }" : "=r"(a) : "l"(p));
    return a;
}
__device__ __forceinline__ u64 packdi(float d, int idx) {
    uint32_t u = __float_as_uint(d);
    u = (u & 0x80000000u) ? ~u : (u | 0x80000000u);
    return ((u64)u << 32) | (uint32_t)idx;
}
__device__ __forceinline__ float unpackd(u64 p) {
    uint32_t u = (uint32_t)(p >> 32);
    u = (u & 0x80000000u) ? (u ^ 0x80000000u) : ~u;
    return __uint_as_float(u);
}
__device__ __forceinline__ float dec_delta(u64 p) {
    return __uint_as_float(((uint32_t)(p & 0x7FFFFu)) << 13);  // <= true delta
}
__device__ __forceinline__ void cpasync16(uint32_t sdst, const void* gsrc) {
    asm volatile("cp.async.cg.shared.global [%0], [%1], 16;" :: "r"(sdst), "l"(gsrc));
}
__device__ __forceinline__ void ldmx4(uint32_t addr, uint32_t& r0, uint32_t& r1,
                                      uint32_t& r2, uint32_t& r3) {
    asm volatile("ldmatrix.sync.aligned.m8n8.x4.shared.b16 {%0,%1,%2,%3}, [%4];"
                 : "=r"(r0), "=r"(r1), "=r"(r2), "=r"(r3) : "r"(addr));
}
__device__ __forceinline__ void mma16816(float* c, const uint32_t* a, const uint32_t* b) {
    asm volatile(
        "mma.sync.aligned.m16n8k16.row.col.f32.f16.f16.f32 "
        "{%0,%1,%2,%3}, {%4,%5,%6,%7}, {%8,%9}, {%0,%1,%2,%3};"
        : "+f"(c[0]), "+f"(c[1]), "+f"(c[2]), "+f"(c[3])
        : "r"(a[0]), "r"(a[1]), "r"(a[2]), "r"(a[3]), "r"(b[0]), "r"(b[1]));
}

// ---------------- prepE: E -> fp16 + ||e||^2 + max norm + inits --------------------
__global__ void prepE_kernel(const float* __restrict__ E, float* out) {
    if (blockIdx.x == 0) {
        if (threadIdx.x == 0) { out[LOSS_OFF] = 0.0f; g_qn = 0; }
        if (threadIdx.x < 128) g_cnt[threadIdx.x] = 0;
    }
    int k = blockIdx.x * 8 + (threadIdx.x >> 5);
    int lane = threadIdx.x & 31;
    const float4* p = (const float4*)(E + (size_t)k * D);
    float4 v0 = p[lane * 2], v1 = p[lane * 2 + 1];
    __half2 h0 = __floats2half2_rn(v0.x, v0.y), h1 = __floats2half2_rn(v0.z, v0.w);
    __half2 h2 = __floats2half2_rn(v1.x, v1.y), h3 = __floats2half2_rn(v1.z, v1.w);
    uint4 o;
    o.x = *(uint32_t*)&h0; o.y = *(uint32_t*)&h1;
    o.z = *(uint32_t*)&h2; o.w = *(uint32_t*)&h3;
    *(uint4*)(g_Bh + (size_t)k * D + lane * 8) = o;
    float s = v0.x*v0.x + v0.y*v0.y + v0.z*v0.z + v0.w*v0.w
            + v1.x*v1.x + v1.y*v1.y + v1.z*v1.z + v1.w*v1.w;
    #pragma unroll
    for (int off = 16; off > 0; off >>= 1) s += __shfl_xor_sync(0xffffffffu, s, off);
    if (lane == 0) {
        g_en2[k] = s;
        atomicMax(&g_maxen, __float_as_int(s));
    }
}

// ---------------- prepA: hs -> g_Ah fp16 + g_Axf fp32 (transposed), row norms ------
__global__ void prepA_kernel(const float* __restrict__ hs) {
    __shared__ float tile[32][33];
    __shared__ float snorm[8][32];
    int m0 = blockIdx.x * 32, b = m0 >> 10, p0 = m0 & 1023;
    int tx = threadIdx.x, ty = threadIdx.y;   // 32 x 8
    float nacc = 0.0f;
    for (int cc = 0; cc < 8; cc++) {
        int c0 = cc * 32;
        __syncthreads();
        #pragma unroll
        for (int i = 0; i < 4; i++) {
            int c = c0 + ty + i * 8;
            float v = hs[((size_t)(b * 256 + c)) * 1024 + p0 + tx];
            tile[ty + i * 8][tx] = v;
            nacc = fmaf(v, v, nacc);
        }
        __syncthreads();
        #pragma unroll
        for (int i = 0; i < 4; i++) {
            int row = ty + i * 8;
            float v = tile[tx][row];
            g_Ah[(size_t)(m0 + row) * D + c0 + tx] = __float2half_rn(v);
            g_Axf[(size_t)(m0 + row) * D + c0 + tx] = v;
        }
    }
    snorm[ty][tx] = nacc;
    __syncthreads();
    if (ty == 0) {
        float tot = 0.0f;
        #pragma unroll
        for (int j = 0; j < 8; j++) tot += snorm[j][tx];
        g_xn2[m0 + tx] = tot;
    }
}

// ---------------- main GEMM (fp16 mma.sync), CTA 128x128, fused merge --------------
#define SA_OFF(b) ((b) * 16384)
#define SB_OFF(b) (32768 + (b) * 16384)
#define SEN_OFF   65536
#define SPART_OFF 66048
#define SMEM_SZ   (1024 + 66048 + 4096)

__global__ void __launch_bounds__(256, 2)
gemm_kernel() {
    extern __shared__ char smem_raw[];
    char* base = (char*)(((uintptr_t)smem_raw + 1023) & ~(uintptr_t)1023);
    uint32_t sb = smem_u32(base);
    float* sEn = (float*)(base + SEN_OFF);
    u64* sPart = (u64*)(base + SPART_OFF);
    __shared__ int slast;

    const int tid = threadIdx.x;
    const int lane = tid & 31, wid = tid >> 5;
    const int wm = wid & 3, wn = wid >> 2;
    const int ntile = blockIdx.x, mtile = blockIdx.y;
    const int m0 = mtile * 128, n0 = ntile * 128;

    if (tid < 128) sEn[tid] = g_en2[n0 + tid];

    auto load_chunk = [&](int c, int bf) {
        #pragma unroll
        for (int it = 0; it < 4; it++) {
            int idx = tid + it * 256;
            int row = idx >> 3, kg = idx & 7;
            uint32_t soff = row * 128 + (((uint32_t)(kg ^ (row & 7))) << 4);
            cpasync16(sb + SA_OFF(bf) + soff,
                      g_Ah + (size_t)(m0 + row) * D + c * 64 + kg * 8);
            cpasync16(sb + SB_OFF(bf) + soff,
                      g_Bh + (size_t)(n0 + row) * D + c * 64 + kg * 8);
        }
        asm volatile("cp.async.commit_group;");
    };

    float acc[2][8][4];
    #pragma unroll
    for (int mt = 0; mt < 2; mt++)
        #pragma unroll
        for (int nt = 0; nt < 8; nt++)
            #pragma unroll
            for (int q = 0; q < 4; q++) acc[mt][nt][q] = 0.0f;

    load_chunk(0, 0);

    for (int c = 0; c < 4; c++) {
        if (c + 1 < 4) {
            load_chunk(c + 1, (c + 1) & 1);
            asm volatile("cp.async.wait_group 1;" ::: "memory");
        } else {
            asm volatile("cp.async.wait_group 0;" ::: "memory");
        }
        __syncthreads();
        uint32_t ab = sb + SA_OFF(c & 1), bbse = sb + SB_OFF(c & 1);
        #pragma unroll
        for (int ks = 0; ks < 4; ks++) {
            uint32_t a[2][4], bb[8][2];
            uint32_t kg = ks * 2 + (lane >> 4);
            uint32_t kx = ((kg ^ (lane & 7)) << 4);
            #pragma unroll
            for (int mt = 0; mt < 2; mt++) {
                uint32_t row = wm * 32 + mt * 16 + (lane & 15);
                ldmx4(ab + row * 128 + kx, a[mt][0], a[mt][1], a[mt][2], a[mt][3]);
            }
            #pragma unroll
            for (int nt2 = 0; nt2 < 4; nt2++) {
                uint32_t row = wn * 64 + nt2 * 16 + (lane & 15);
                uint32_t r0, r1, r2, r3;
                ldmx4(bbse + row * 128 + kx, r0, r1, r2, r3);
                bb[nt2 * 2][0] = r0; bb[nt2 * 2][1] = r2;
                bb[nt2 * 2 + 1][0] = r1; bb[nt2 * 2 + 1][1] = r3;
            }
            #pragma unroll
            for (int mt = 0; mt < 2; mt++)
                #pragma unroll
                for (int nt = 0; nt < 8; nt++)
                    mma16816(acc[mt][nt], a[mt], bb[nt]);
        }
        __syncthreads();
    }

    // epilogue: per-row top-2 of dist = en2 - 2*dot within this 128-col tile
    #pragma unroll
    for (int mt = 0; mt < 2; mt++) {
        #pragma unroll
        for (int half = 0; half < 2; half++) {
            u64 t1 = ~0ull, t2 = ~0ull;
            #pragma unroll
            for (int nt = 0; nt < 8; nt++) {
                #pragma unroll
                for (int cc = 0; cc < 2; cc++) {
                    int col = wn * 64 + nt * 8 + (lane & 3) * 2 + cc;
                    float dist = fmaf(-2.0f, acc[mt][nt][half * 2 + cc], sEn[col]);
                    u64 pk = packdi(dist, n0 + col);
                    if (pk < t1) { t2 = t1; t1 = pk; }
                    else if (pk < t2) { t2 = pk; }
                }
            }
            #pragma unroll
            for (int dlt = 1; dlt <= 2; dlt <<= 1) {
                u64 o1 = __shfl_xor_sync(0xffffffffu, t1, dlt);
                u64 o2 = __shfl_xor_sync(0xffffffffu, t2, dlt);
                u64 n1 = min(t1, o1);
                u64 n2 = min(max(t1, o1), min(t2, o2));
                t1 = n1; t2 = n2;
            }
            if ((lane & 3) == 0) {
                int rl = wm * 32 + mt * 16 + half * 8 + (lane >> 2);
                sPart[rl * 4 + wn * 2] = t1;
                sPart[rl * 4 + wn * 2 + 1] = t2;
            }
        }
    }
    __syncthreads();
    if (tid < 128) {
        u64 p1 = ~0ull, p2 = ~0ull;
        #pragma unroll
        for (int w = 0; w < 2; w++) {
            u64 a1 = sPart[tid * 4 + w * 2], a2 = sPart[tid * 4 + w * 2 + 1];
            u64 n1 = min(p1, a1);
            u64 n2 = min(max(p1, a1), min(p2, a2));
            p1 = n1; p2 = n2;
        }
        // pack: [orderable d1 (32)] [idx (13)] [delta trunc-fp32 (19)]
        float d1 = unpackd(p1), d2 = unpackd(p2);
        uint32_t dq = __float_as_uint(fmaxf(d2 - d1, 0.0f)) >> 13;  // round down
        u64 packed = ((p1 >> 32) << 32)
                   | (((p1 & 0xFFFFFFFFull) & 0x1FFFull) << 19)
                   | (u64)(dq & 0x7FFFFu);
        g_part[(size_t)(m0 + tid) * 64 + ntile] = packed;
    }
    __threadfence();
    __syncthreads();
    if (tid == 0) slast = (atomicAdd(&g_cnt[mtile], 1) == 63) ? 1 : 0;
    __syncthreads();
    if (!slast) return;
    __threadfence();

    // fused merge_fast: this CTA's 8 warps handle the 128 rows of mtile
    for (int it = 0; it < 16; it++) {
        int r = m0 + wid * 16 + it;
        const u64* pr = g_part + (size_t)r * 64;
        u64 e0 = __ldcg(pr + lane * 2);
        u64 e1 = __ldcg(pr + lane * 2 + 1);
        u64 m = min(e0, e1);
        #pragma unroll
        for (int o = 16; o > 0; o >>= 1) m = min(m, __shfl_xor_sync(0xffffffffu, m, o));
        float pad = 0.00196f * sqrtf(__ldg(&g_xn2[r]) * __int_as_float(g_maxen)) + 0.05f;
        float thr = unpackd(m) + pad;

        float d10 = unpackd(e0), d11 = unpackd(e1);
        float d20 = d10 + dec_delta(e0), d21 = d11 + dec_delta(e1);
        bool f0 = d20 <= thr, f1 = d21 <= thr;
        bool c0 = (!f0) && (d10 <= thr);
        bool c1 = (!f1) && (d11 <= thr);
        unsigned mf = __ballot_sync(0xffffffffu, f0 | f1);
        int nc = __popc(__ballot_sync(0xffffffffu, c0))
               + __popc(__ballot_sync(0xffffffffu, c1));

        if (mf == 0 && nc == 1) {
            if (lane == 0) g_idx[r] = (int)((m >> 19) & 0x1FFFu);
        } else {
            if (lane == 0) { g_best[r] = ~0ull; g_idx[r] = -1; }
            int rsh = r << 13;
            if (c0) {
                int q = atomicAdd(&g_qn, 1);
                if (q < QCAP) g_queue[q] = rsh | (int)((e0 >> 19) & 0x1FFFu);
            }
            if (c1) {
                int q = atomicAdd(&g_qn, 1);
                if (q < QCAP) g_queue[q] = rsh | (int)((e1 >> 19) & 0x1FFFu);
            }
            if (f0) {
                int q = atomicAdd(&g_qn, 128);
                int k0 = (lane * 2) * 128;
                for (int i = 0; i < 128 && q + i < QCAP; i++)
                    g_queue[q + i] = rsh | (k0 + i);
            }
            if (f1) {
                int q = atomicAdd(&g_qn, 128);
                int k0 = (lane * 2 + 1) * 128;
                for (int i = 0; i < 128 && q + i < QCAP; i++)
                    g_queue[q + i] = rsh | (k0 + i);
            }
        }
    }
}

// ---------------- merge_slow: one warp per candidate task ---------------------------
__global__ void __launch_bounds__(256, 8)
merge_slow_kernel(const float* __restrict__ E) {
    int nt = g_qn;
    if (nt > QCAP) nt = QCAP;
    int lane = threadIdx.x & 31;
    int gw = (blockIdx.x * 256 + threadIdx.x) >> 5;
    int nwarp = (gridDim.x * 256) >> 5;

    for (int t = gw; t < nt; t += nwarp) {
        int task = g_queue[t];
        int row = task >> 13, k = task & 0x1FFF;
        const float* xr = g_Axf + (size_t)row * D;
        const float* ek = E + (size_t)k * D;
        float s = 0.0f;
        #pragma unroll
        for (int j = 0; j < 8; j++)
            s = fmaf(__ldg(xr + lane + j * 32), __ldg(ek + lane + j * 32), s);
        #pragma unroll
        for (int o = 16; o > 0; o >>= 1) s += __shfl_xor_sync(0xffffffffu, s, o);
        if (lane == 0) {
            float dist = fmaf(-2.0f, s, __ldg(&g_en2[k]));
            atomicMin(&g_best[row], packdi(dist, k));
        }
    }
}

// ---------------- final gather + loss (float4), resolves slow rows ------------------
__global__ void final_kernel(const float* __restrict__ hs,
                             const float* __restrict__ E,
                             float* __restrict__ out) {
    __shared__ int sIdx[128];
    __shared__ float sRed[8];
    int tid = threadIdx.x;
    int lane = tid & 31;
    int row0 = blockIdx.x * 128;
    int b = row0 >> 10, p0 = row0 & 1023;
    size_t xbase = (size_t)b * 256 * 1024 + p0;

    if (tid < 128) {
        int k = g_idx[row0 + tid];
        if (k < 0) k = (int)(g_best[row0 + tid] & 0xFFFFFFFFu);
        sIdx[tid] = k;
        out[IDX_OFF + row0 + tid] = (float)k;
    }
    __syncthreads();

    int k0 = sIdx[lane * 4], k1 = sIdx[lane * 4 + 1];
    int k2 = sIdx[lane * 4 + 2], k3 = sIdx[lane * 4 + 3];

    float lsum = 0.0f;
    #pragma unroll 4
    for (int i = 0; i < 32; i++) {
        int c = i * 8 + (tid >> 5);
        size_t ad = xbase + (size_t)c * 1024 + lane * 4;
        float4 xv = *(const float4*)(hs + ad);
        float4 ev;
        ev.x = __ldg(E + (size_t)k0 * D + c);
        ev.y = __ldg(E + (size_t)k1 * D + c);
        ev.z = __ldg(E + (size_t)k2 * D + c);
        ev.w = __ldg(E + (size_t)k3 * D + c);
        *(float4*)(out + ad) = ev;
        float d0 = ev.x - xv.x, d1 = ev.y - xv.y;
        float d2 = ev.z - xv.z, d3 = ev.w - xv.w;
        lsum = fmaf(d0, d0, lsum);
        lsum = fmaf(d1, d1, lsum);
        lsum = fmaf(d2, d2, lsum);
        lsum = fmaf(d3, d3, lsum);
    }
    #pragma unroll
    for (int o = 16; o > 0; o >>= 1) lsum += __shfl_xor_sync(0xffffffffu, lsum, o);
    if ((tid & 31) == 0) sRed[tid >> 5] = lsum;
    __syncthreads();
    if (tid == 0) {
        float tot = 0.0f;
        #pragma unroll
        for (int w = 0; w < 8; w++) tot += sRed[w];
        atomicAdd(out + LOSS_OFF, tot * (1.25f / 4194304.0f));
    }
}

extern "C" void kernel_launch(void* const* d_in, const int* in_sizes, int n_in,
                              void* d_out, int out_size) {
    const float* hs = (const float*)d_in[0];
    const float* E  = (const float*)d_in[1];
    float* out = (float*)d_out;

    cudaFuncSetAttribute(gemm_kernel,
                         cudaFuncAttributeMaxDynamicSharedMemorySize, SMEM_SZ);

    prepE_kernel<<<KC / 8, 256>>>(E, out);
    prepA_kernel<<<N_ROWS / 32, dim3(32, 8)>>>(hs);
    gemm_kernel<<<dim3(KC / 128, N_ROWS / 128), 256, SMEM_SZ>>>();
    merge_slow_kernel<<<592, 256>>>(E);
    final_kernel<<<N_ROWS / 128, 256>>>(hs, E, out);
}

// round 15
// speedup vs baseline: 1.3010x; 1.2050x over previous
#include <cuda_runtime.h>
#include <cstdint>

// ---------------- problem constants ----------------
#define N_ROWS 16384
#define KC 8192
#define D 256
#define LOSS_OFF 4194304
#define IDX_OFF 4194305
#define QCAP (1 << 20)

typedef unsigned long long u64;

// ---------------- device scratch ----------------
__device__ uint2 g_A8[(size_t)N_ROWS * 32];   // x int8 [m][256] (uint2 = 8 bytes)
__device__ uint2 g_B8[(size_t)KC * 32];       // e int8 [n][256]
__device__ float g_Axf[(size_t)N_ROWS * D];   // x fp32 row-major (exact recheck)
__device__ float g_en2[KC];                   // ||e||^2 fp32
__device__ float g_xn2[N_ROWS];               // ||x||^2 per row
__device__ float g_invsx[N_ROWS];             // 1/s_x per row
__device__ float g_invse[KC];                 // 1/s_e per code
__device__ int g_maxen = 0;                   // max ||e||^2 bits (atomicMax, idempotent)
__device__ int g_maxive = 0;                  // max inv_se bits
__device__ u64 g_part[(size_t)N_ROWS * 128];  // per row: 64 tiles x top-2
__device__ int g_idx[N_ROWS];
__device__ u64 g_best[N_ROWS];
__device__ int g_queue[QCAP];                 // candidate tasks: (row<<13)|k
__device__ int g_rowq[N_ROWS];
__device__ int g_qn;
__device__ int g_rqn;

// ---------------- helpers ----------------
__device__ __forceinline__ uint32_t smem_u32(const void* p) {
    uint32_t a;
    asm("{ .reg .u64 t; cvta.to.shared.u64 t, %1; cvt.u32.u64 %0, t; }" : "=r"(a) : "l"(p));
    return a;
}
__device__ __forceinline__ u64 packdi(float d, int idx) {
    uint32_t u = __float_as_uint(d);
    u = (u & 0x80000000u) ? ~u : (u | 0x80000000u);
    return ((u64)u << 32) | (uint32_t)idx;
}
__device__ __forceinline__ float unpackd(u64 p) {
    uint32_t u = (uint32_t)(p >> 32);
    u = (u & 0x80000000u) ? (u ^ 0x80000000u) : ~u;
    return __uint_as_float(u);
}
__device__ __forceinline__ void cpasync16(uint32_t sdst, const void* gsrc) {
    asm volatile("cp.async.cg.shared.global [%0], [%1], 16;" :: "r"(sdst), "l"(gsrc));
}
__device__ __forceinline__ void ldmx4(uint32_t addr, uint32_t& r0, uint32_t& r1,
                                      uint32_t& r2, uint32_t& r3) {
    asm volatile("ldmatrix.sync.aligned.m8n8.x4.shared.b16 {%0,%1,%2,%3}, [%4];"
                 : "=r"(r0), "=r"(r1), "=r"(r2), "=r"(r3) : "r"(addr));
}
// int8 MMA: s32 += s8 x s8, m16n8k32
__device__ __forceinline__ void mma16832i(int* c, const uint32_t* a, const uint32_t* b) {
    asm volatile(
        "mma.sync.aligned.m16n8k32.row.col.s32.s8.s8.s32 "
        "{%0,%1,%2,%3}, {%4,%5,%6,%7}, {%8,%9}, {%0,%1,%2,%3};"
        : "+r"(c[0]), "+r"(c[1]), "+r"(c[2]), "+r"(c[3])
        : "r"(a[0]), "r"(a[1]), "r"(a[2]), "r"(a[3]), "r"(b[0]), "r"(b[1]));
}
__device__ __forceinline__ uint32_t pack4i8(float a, float b, float c, float d, float s) {
    int q0 = (int)rintf(a * s), q1 = (int)rintf(b * s);
    int q2 = (int)rintf(c * s), q3 = (int)rintf(d * s);
    return (q0 & 255) | ((q1 & 255) << 8) | ((q2 & 255) << 16) | ((q3 & 255) << 24);
}

// ---------------- prepE: E -> int8 + scales + ||e||^2 + inits ----------------------
__global__ void prepE_kernel(const float* __restrict__ E, float* out) {
    int k = blockIdx.x * 8 + (threadIdx.x >> 5);
    int lane = threadIdx.x & 31;
    if (blockIdx.x == 0 && threadIdx.x == 0) { out[LOSS_OFF] = 0.0f; g_qn = 0; g_rqn = 0; }
    const float4* p = (const float4*)(E + (size_t)k * D);
    float4 v0 = p[lane * 2], v1 = p[lane * 2 + 1];
    float s = v0.x*v0.x + v0.y*v0.y + v0.z*v0.z + v0.w*v0.w
            + v1.x*v1.x + v1.y*v1.y + v1.z*v1.z + v1.w*v1.w;
    float mx = fmaxf(fmaxf(fmaxf(fabsf(v0.x), fabsf(v0.y)), fmaxf(fabsf(v0.z), fabsf(v0.w))),
                     fmaxf(fmaxf(fabsf(v1.x), fabsf(v1.y)), fmaxf(fabsf(v1.z), fabsf(v1.w))));
    #pragma unroll
    for (int o = 16; o > 0; o >>= 1) {
        s += __shfl_xor_sync(0xffffffffu, s, o);
        mx = fmaxf(mx, __shfl_xor_sync(0xffffffffu, mx, o));
    }
    float scale = 126.0f / mx;
    float inv = mx * (1.0f / 126.0f);
    uint2 q;
    q.x = pack4i8(v0.x, v0.y, v0.z, v0.w, scale);
    q.y = pack4i8(v1.x, v1.y, v1.z, v1.w, scale);
    g_B8[(size_t)k * 32 + lane] = q;
    if (lane == 0) {
        g_en2[k] = s;
        g_invse[k] = inv;
        atomicMax(&g_maxen, __float_as_int(s));
        atomicMax(&g_maxive, __float_as_int(inv));
    }
}

// ---------------- prepA: hs -> g_Axf fp32 (transposed) + int8 quant + row stats ----
__global__ void prepA_kernel(const float* __restrict__ hs) {
    __shared__ float tile[32][33];
    __shared__ float snorm[8][32];
    __shared__ float smax[8][32];
    __shared__ float sScale[32];
    int m0 = blockIdx.x * 32, b = m0 >> 10, p0 = m0 & 1023;
    int tx = threadIdx.x, ty = threadIdx.y;   // 32 x 8
    float nacc = 0.0f, macc = 0.0f;
    for (int cc = 0; cc < 8; cc++) {
        int c0 = cc * 32;
        __syncthreads();
        #pragma unroll
        for (int i = 0; i < 4; i++) {
            int c = c0 + ty + i * 8;
            float v = hs[((size_t)(b * 256 + c)) * 1024 + p0 + tx];
            tile[ty + i * 8][tx] = v;
            nacc = fmaf(v, v, nacc);
            macc = fmaxf(macc, fabsf(v));
        }
        __syncthreads();
        #pragma unroll
        for (int i = 0; i < 4; i++) {
            int row = ty + i * 8;
            g_Axf[(size_t)(m0 + row) * D + c0 + tx] = tile[tx][row];
        }
    }
    snorm[ty][tx] = nacc;
    smax[ty][tx] = macc;
    __syncthreads();
    if (ty == 0) {
        float tot = 0.0f, mx = 0.0f;
        #pragma unroll
        for (int j = 0; j < 8; j++) { tot += snorm[j][tx]; mx = fmaxf(mx, smax[j][tx]); }
        g_xn2[m0 + tx] = tot;
        float scale = 126.0f / mx;
        g_invsx[m0 + tx] = mx * (1.0f / 126.0f);
        sScale[tx] = scale;
    }
    __syncthreads();
    // fused quantization: FULL coverage — 32 rows x 32 segs (8B each), 4 per thread
    int tid = ty * 32 + tx;
    #pragma unroll
    for (int i = 0; i < 4; i++) {
        int t = tid + i * 256;              // 0..1023
        int r = t >> 5, seg = t & 31;       // row 0..31, seg 0..31 (8 floats each)
        const float4* src = (const float4*)(g_Axf + (size_t)(m0 + r) * D + seg * 8);
        float4 a = src[0], c = src[1];
        float s = sScale[r];
        uint2 q;
        q.x = pack4i8(a.x, a.y, a.z, a.w, s);
        q.y = pack4i8(c.x, c.y, c.z, c.w, s);
        g_A8[(size_t)(m0 + r) * 32 + seg] = q;
    }
}

// ---------------- main GEMM (int8 mma.sync), CTA 128x128, 2-stage ------------------
#define SA_OFF(b) ((b) * 16384)
#define SB_OFF(b) (32768 + (b) * 16384)
#define SEN_OFF   65536
#define SIV_OFF   66048
#define SIX_OFF   66560
#define SPART_OFF 67072
#define SMEM_SZ   (1024 + 67072 + 4096)

__global__ void __launch_bounds__(256, 2)
gemm_kernel() {
    extern __shared__ char smem_raw[];
    char* base = (char*)(((uintptr_t)smem_raw + 1023) & ~(uintptr_t)1023);
    uint32_t sb = smem_u32(base);
    float* sEn = (float*)(base + SEN_OFF);
    float* sIv = (float*)(base + SIV_OFF);
    float* sIx = (float*)(base + SIX_OFF);
    u64* sPart = (u64*)(base + SPART_OFF);

    const int tid = threadIdx.x;
    const int lane = tid & 31, wid = tid >> 5;
    const int wm = wid & 3, wn = wid >> 2;
    const int ntile = blockIdx.x, mtile = blockIdx.y;
    const int m0 = mtile * 128, n0 = ntile * 128;

    if (tid < 128) {
        sEn[tid] = g_en2[n0 + tid];
        sIv[tid] = g_invse[n0 + tid];
        sIx[tid] = g_invsx[m0 + tid];
    }

    auto load_chunk = [&](int c, int bf) {
        #pragma unroll
        for (int it = 0; it < 4; it++) {
            int idx = tid + it * 256;
            int row = idx >> 3, kg = idx & 7;
            uint32_t soff = row * 128 + (((uint32_t)(kg ^ (row & 7))) << 4);
            cpasync16(sb + SA_OFF(bf) + soff,
                      (const char*)g_A8 + (size_t)(m0 + row) * 256 + c * 128 + kg * 16);
            cpasync16(sb + SB_OFF(bf) + soff,
                      (const char*)g_B8 + (size_t)(n0 + row) * 256 + c * 128 + kg * 16);
        }
        asm volatile("cp.async.commit_group;");
    };

    int acc[2][8][4];
    #pragma unroll
    for (int mt = 0; mt < 2; mt++)
        #pragma unroll
        for (int nt = 0; nt < 8; nt++)
            #pragma unroll
            for (int q = 0; q < 4; q++) acc[mt][nt][q] = 0;

    load_chunk(0, 0);

    for (int c = 0; c < 2; c++) {
        if (c + 1 < 2) {
            load_chunk(c + 1, (c + 1) & 1);
            asm volatile("cp.async.wait_group 1;" ::: "memory");
        } else {
            asm volatile("cp.async.wait_group 0;" ::: "memory");
        }
        __syncthreads();
        uint32_t ab = sb + SA_OFF(c & 1), bbse = sb + SB_OFF(c & 1);
        #pragma unroll
        for (int ks = 0; ks < 4; ks++) {
            uint32_t a[2][4], bb[8][2];
            uint32_t kg = ks * 2 + (lane >> 4);
            uint32_t kx = ((kg ^ (lane & 7)) << 4);
            #pragma unroll
            for (int mt = 0; mt < 2; mt++) {
                uint32_t row = wm * 32 + mt * 16 + (lane & 15);
                ldmx4(ab + row * 128 + kx, a[mt][0], a[mt][1], a[mt][2], a[mt][3]);
            }
            #pragma unroll
            for (int nt2 = 0; nt2 < 4; nt2++) {
                uint32_t row = wn * 64 + nt2 * 16 + (lane & 15);
                uint32_t r0, r1, r2, r3;
                ldmx4(bbse + row * 128 + kx, r0, r1, r2, r3);
                bb[nt2 * 2][0] = r0; bb[nt2 * 2][1] = r2;
                bb[nt2 * 2 + 1][0] = r1; bb[nt2 * 2 + 1][1] = r3;
            }
            #pragma unroll
            for (int mt = 0; mt < 2; mt++)
                #pragma unroll
                for (int nt = 0; nt < 8; nt++)
                    mma16832i(acc[mt][nt], a[mt], bb[nt]);
        }
        __syncthreads();
    }

    // epilogue: dist = en2 - 2*inv_sx*inv_se*dot_int ; per-row top-2 within tile
    #pragma unroll
    for (int mt = 0; mt < 2; mt++) {
        #pragma unroll
        for (int half = 0; half < 2; half++) {
            int rl = wm * 32 + mt * 16 + half * 8 + (lane >> 2);
            float m2ivx = -2.0f * sIx[rl];
            u64 t1 = ~0ull, t2 = ~0ull;
            #pragma unroll
            for (int nt = 0; nt < 8; nt++) {
                #pragma unroll
                for (int cc = 0; cc < 2; cc++) {
                    int col = wn * 64 + nt * 8 + (lane & 3) * 2 + cc;
                    float dist = fmaf((float)acc[mt][nt][half * 2 + cc],
                                      m2ivx * sIv[col], sEn[col]);
                    u64 pk = packdi(dist, n0 + col);
                    if (pk < t1) { t2 = t1; t1 = pk; }
                    else if (pk < t2) { t2 = pk; }
                }
            }
            #pragma unroll
            for (int dlt = 1; dlt <= 2; dlt <<= 1) {
                u64 o1 = __shfl_xor_sync(0xffffffffu, t1, dlt);
                u64 o2 = __shfl_xor_sync(0xffffffffu, t2, dlt);
                u64 n1 = min(t1, o1);
                u64 n2 = min(max(t1, o1), min(t2, o2));
                t1 = n1; t2 = n2;
            }
            if ((lane & 3) == 0) {
                sPart[rl * 4 + wn * 2] = t1;
                sPart[rl * 4 + wn * 2 + 1] = t2;
            }
        }
    }
    __syncthreads();
    if (tid < 128) {
        u64 a1 = sPart[tid * 4], a2 = sPart[tid * 4 + 1];
        u64 b1 = sPart[tid * 4 + 2], b2 = sPart[tid * 4 + 3];
        u64 n1 = min(a1, b1);
        u64 n2 = min(max(a1, b1), min(a2, b2));
        g_part[(size_t)(m0 + tid) * 128 + ntile * 2] = n1;
        g_part[(size_t)(m0 + tid) * 128 + ntile * 2 + 1] = n2;
    }
}

// ---------------- merge_fast: warp/row, fast path or enqueue candidate tasks --------
__global__ void merge_fast_kernel(float* __restrict__ out) {
    int wid = threadIdx.x >> 5, lane = threadIdx.x & 31;
    int row = blockIdx.x * 8 + wid;

    const ulonglong2* pp = (const ulonglong2*)(g_part + (size_t)row * 128);
    ulonglong2 ea = pp[lane * 2], eb = pp[lane * 2 + 1];

    u64 m = min(min(ea.x, ea.y), min(eb.x, eb.y));
    #pragma unroll
    for (int o = 16; o > 0; o >>= 1) m = min(m, __shfl_xor_sync(0xffffffffu, m, o));

    // int8 quantization pad: ~9 sigma of dist error
    float ivx = __ldg(&g_invsx[row]);
    float ive = __int_as_float(g_maxive);
    float pad = 5.2f * sqrtf(ivx * ivx * __int_as_float(g_maxen)
                             + ive * ive * __ldg(&g_xn2[row])) + 0.1f;
    float thr = unpackd(m) + pad;

    bool f0 = unpackd(ea.y) <= thr;
    bool f1 = unpackd(eb.y) <= thr;
    bool c0 = (!f0) && (unpackd(ea.x) <= thr);
    bool c1 = (!f1) && (unpackd(eb.x) <= thr);
    unsigned mf = __ballot_sync(0xffffffffu, f0 | f1);
    int nc = (int)c0 + (int)c1;
    #pragma unroll
    for (int o = 16; o > 0; o >>= 1) nc += __shfl_xor_sync(0xffffffffu, nc, o);

    if (mf == 0 && nc == 1) {
        if (lane == 0) {
            int k = (int)(m & 0xFFFFFFFFu);
            g_idx[row] = k;
            out[IDX_OFF + row] = (float)k;
        }
        return;
    }

    if (lane == 0) {
        g_best[row] = ~0ull;
        g_rowq[atomicAdd(&g_rqn, 1)] = row;
    }
    int rsh = row << 13;
    if (c0) {
        int q = atomicAdd(&g_qn, 1);
        if (q < QCAP) g_queue[q] = rsh | (int)(ea.x & 0x1FFFu);
    }
    if (c1) {
        int q = atomicAdd(&g_qn, 1);
        if (q < QCAP) g_queue[q] = rsh | (int)(eb.x & 0x1FFFu);
    }
    if (f0) {
        int q = atomicAdd(&g_qn, 128);
        int k0 = (lane * 2) * 128;
        for (int i = 0; i < 128 && q + i < QCAP; i++) g_queue[q + i] = rsh | (k0 + i);
    }
    if (f1) {
        int q = atomicAdd(&g_qn, 128);
        int k0 = (lane * 2 + 1) * 128;
        for (int i = 0; i < 128 && q + i < QCAP; i++) g_queue[q + i] = rsh | (k0 + i);
    }
}

// ---------------- merge_slow: one warp per candidate task ---------------------------
__global__ void __launch_bounds__(256, 8)
merge_slow_kernel(const float* __restrict__ E) {
    int nt = g_qn;
    if (nt > QCAP) nt = QCAP;
    int lane = threadIdx.x & 31;
    int gw = (blockIdx.x * 256 + threadIdx.x) >> 5;
    int nwarp = (gridDim.x * 256) >> 5;

    for (int t = gw; t < nt; t += nwarp) {
        int task = g_queue[t];
        int row = task >> 13, k = task & 0x1FFF;
        const float* xr = g_Axf + (size_t)row * D;
        const float* ek = E + (size_t)k * D;
        float s = 0.0f;
        #pragma unroll
        for (int j = 0; j < 8; j++)
            s = fmaf(__ldg(xr + lane + j * 32), __ldg(ek + lane + j * 32), s);
        #pragma unroll
        for (int o = 16; o > 0; o >>= 1) s += __shfl_xor_sync(0xffffffffu, s, o);
        if (lane == 0) {
            float dist = fmaf(-2.0f, s, __ldg(&g_en2[k]));
            atomicMin(&g_best[row], packdi(dist, k));
        }
    }
}

// ---------------- merge_fin: finalize queued rows ------------------------------------
__global__ void merge_fin_kernel(float* __restrict__ out) {
    int n = g_rqn;
    for (int i = blockIdx.x * 256 + threadIdx.x; i < n; i += gridDim.x * 256) {
        int row = g_rowq[i];
        int k = (int)(g_best[row] & 0xFFFFFFFFu);
        g_idx[row] = k;
        out[IDX_OFF + row] = (float)k;
    }
}

// ---------------- final gather + loss (float4) --------------------------------------
__global__ void final_kernel(const float* __restrict__ hs,
                             const float* __restrict__ E,
                             float* __restrict__ out) {
    __shared__ int sIdx[128];
    __shared__ float sRed[8];
    int tid = threadIdx.x;
    int lane = tid & 31;
    int row0 = blockIdx.x * 128;
    int b = row0 >> 10, p0 = row0 & 1023;
    size_t xbase = (size_t)b * 256 * 1024 + p0;

    if (tid < 128) sIdx[tid] = g_idx[row0 + tid];
    __syncthreads();

    int k0 = sIdx[lane * 4], k1 = sIdx[lane * 4 + 1];
    int k2 = sIdx[lane * 4 + 2], k3 = sIdx[lane * 4 + 3];

    float lsum = 0.0f;
    #pragma unroll 4
    for (int i = 0; i < 32; i++) {
        int c = i * 8 + (tid >> 5);
        size_t ad = xbase + (size_t)c * 1024 + lane * 4;
        float4 xv = *(const float4*)(hs + ad);
        float4 ev;
        ev.x = __ldg(E + (size_t)k0 * D + c);
        ev.y = __ldg(E + (size_t)k1 * D + c);
        ev.z = __ldg(E + (size_t)k2 * D + c);
        ev.w = __ldg(E + (size_t)k3 * D + c);
        *(float4*)(out + ad) = ev;
        float d0 = ev.x - xv.x, d1 = ev.y - xv.y;
        float d2 = ev.z - xv.z, d3 = ev.w - xv.w;
        lsum = fmaf(d0, d0, lsum);
        lsum = fmaf(d1, d1, lsum);
        lsum = fmaf(d2, d2, lsum);
        lsum = fmaf(d3, d3, lsum);
    }
    #pragma unroll
    for (int o = 16; o > 0; o >>= 1) lsum += __shfl_xor_sync(0xffffffffu, lsum, o);
    if ((tid & 31) == 0) sRed[tid >> 5] = lsum;
    __syncthreads();
    if (tid == 0) {
        float tot = 0.0f;
        #pragma unroll
        for (int w = 0; w < 8; w++) tot += sRed[w];
        atomicAdd(out + LOSS_OFF, tot * (1.25f / 4194304.0f));
    }
}

extern "C" void kernel_launch(void* const* d_in, const int* in_sizes, int n_in,
                              void* d_out, int out_size) {
    const float* hs = (const float*)d_in[0];
    const float* E  = (const float*)d_in[1];
    float* out = (float*)d_out;

    cudaFuncSetAttribute(gemm_kernel,
                         cudaFuncAttributeMaxDynamicSharedMemorySize, SMEM_SZ);

    prepE_kernel<<<KC / 8, 256>>>(E, out);
    prepA_kernel<<<N_ROWS / 32, dim3(32, 8)>>>(hs);
    gemm_kernel<<<dim3(KC / 128, N_ROWS / 128), 256, SMEM_SZ>>>();
    merge_fast_kernel<<<N_ROWS / 8, 256>>>(out);
    merge_slow_kernel<<<592, 256>>>(E);
    merge_fin_kernel<<<32, 256>>>(out);
    final_kernel<<<N_ROWS / 128, 256>>>(hs, E, out);
}

// round 16
// speedup vs baseline: 1.3983x; 1.0748x over previous
#include <cuda_runtime.h>
#include <cstdint>

// ---------------- problem constants ----------------
#define N_ROWS 16384
#define KC 8192
#define D 256
#define LOSS_OFF 4194304
#define IDX_OFF 4194305
#define QCAP (1 << 20)

typedef unsigned long long u64;

// ---------------- device scratch ----------------
__device__ uint2 g_A8[(size_t)N_ROWS * 32];   // x int8 [m][256] (uint2 = 8 bytes)
__device__ uint2 g_B8[(size_t)KC * 32];       // e int8 [n][256]
__device__ float g_Axf[(size_t)N_ROWS * D];   // x fp32 row-major (exact recheck)
__device__ float g_en2[KC];                   // ||e||^2 fp32
__device__ float g_xn2[N_ROWS];               // ||x||^2 per row
__device__ float g_invsx[N_ROWS];             // 1/s_x per row
__device__ float g_invse[KC];                 // 1/s_e per code
__device__ int g_maxen = 0;                   // max ||e||^2 bits (atomicMax, idempotent)
__device__ int g_maxive = 0;                  // max inv_se bits
__device__ u64 g_part[(size_t)N_ROWS * 64];   // per row: 64 tiles x packed[d1|idx13|dq19]
__device__ int g_idx[N_ROWS];
__device__ u64 g_best[N_ROWS];
__device__ int g_queue[QCAP];                 // candidate tasks: (row<<13)|k
__device__ int g_rowq[N_ROWS];
__device__ int g_qn;
__device__ int g_rqn;

// ---------------- helpers ----------------
__device__ __forceinline__ uint32_t smem_u32(const void* p) {
    uint32_t a;
    asm("{ .reg .u64 t; cvta.to.shared.u64 t, %1; cvt.u32.u64 %0, t; }" : "=r"(a) : "l"(p));
    return a;
}
__device__ __forceinline__ u64 packdi(float d, int idx) {
    uint32_t u = __float_as_uint(d);
    u = (u & 0x80000000u) ? ~u : (u | 0x80000000u);
    return ((u64)u << 32) | (uint32_t)idx;
}
__device__ __forceinline__ float unpackd(u64 p) {
    uint32_t u = (uint32_t)(p >> 32);
    u = (u & 0x80000000u) ? (u ^ 0x80000000u) : ~u;
    return __uint_as_float(u);
}
__device__ __forceinline__ float dec_delta(u64 p) {
    return __uint_as_float(((uint32_t)(p & 0x7FFFFu)) << 13);  // <= true delta
}
__device__ __forceinline__ void cpasync16(uint32_t sdst, const void* gsrc) {
    asm volatile("cp.async.cg.shared.global [%0], [%1], 16;" :: "r"(sdst), "l"(gsrc));
}
__device__ __forceinline__ void ldmx4(uint32_t addr, uint32_t& r0, uint32_t& r1,
                                      uint32_t& r2, uint32_t& r3) {
    asm volatile("ldmatrix.sync.aligned.m8n8.x4.shared.b16 {%0,%1,%2,%3}, [%4];"
                 : "=r"(r0), "=r"(r1), "=r"(r2), "=r"(r3) : "r"(addr));
}
// int8 MMA: s32 += s8 x s8, m16n8k32
__device__ __forceinline__ void mma16832i(int* c, const uint32_t* a, const uint32_t* b) {
    asm volatile(
        "mma.sync.aligned.m16n8k32.row.col.s32.s8.s8.s32 "
        "{%0,%1,%2,%3}, {%4,%5,%6,%7}, {%8,%9}, {%0,%1,%2,%3};"
        : "+r"(c[0]), "+r"(c[1]), "+r"(c[2]), "+r"(c[3])
        : "r"(a[0]), "r"(a[1]), "r"(a[2]), "r"(a[3]), "r"(b[0]), "r"(b[1]));
}
__device__ __forceinline__ uint32_t pack4i8(float a, float b, float c, float d, float s) {
    int q0 = (int)rintf(a * s), q1 = (int)rintf(b * s);
    int q2 = (int)rintf(c * s), q3 = (int)rintf(d * s);
    return (q0 & 255) | ((q1 & 255) << 8) | ((q2 & 255) << 16) | ((q3 & 255) << 24);
}

// ---------------- prepE: E -> int8 + scales + ||e||^2 + inits ----------------------
__global__ void prepE_kernel(const float* __restrict__ E, float* out) {
    int k = blockIdx.x * 8 + (threadIdx.x >> 5);
    int lane = threadIdx.x & 31;
    if (blockIdx.x == 0 && threadIdx.x == 0) { out[LOSS_OFF] = 0.0f; g_qn = 0; g_rqn = 0; }
    const float4* p = (const float4*)(E + (size_t)k * D);
    float4 v0 = p[lane * 2], v1 = p[lane * 2 + 1];
    float s = v0.x*v0.x + v0.y*v0.y + v0.z*v0.z + v0.w*v0.w
            + v1.x*v1.x + v1.y*v1.y + v1.z*v1.z + v1.w*v1.w;
    float mx = fmaxf(fmaxf(fmaxf(fabsf(v0.x), fabsf(v0.y)), fmaxf(fabsf(v0.z), fabsf(v0.w))),
                     fmaxf(fmaxf(fabsf(v1.x), fabsf(v1.y)), fmaxf(fabsf(v1.z), fabsf(v1.w))));
    #pragma unroll
    for (int o = 16; o > 0; o >>= 1) {
        s += __shfl_xor_sync(0xffffffffu, s, o);
        mx = fmaxf(mx, __shfl_xor_sync(0xffffffffu, mx, o));
    }
    float scale = 126.0f / mx;
    float inv = mx * (1.0f / 126.0f);
    uint2 q;
    q.x = pack4i8(v0.x, v0.y, v0.z, v0.w, scale);
    q.y = pack4i8(v1.x, v1.y, v1.z, v1.w, scale);
    g_B8[(size_t)k * 32 + lane] = q;
    if (lane == 0) {
        g_en2[k] = s;
        g_invse[k] = inv;
        atomicMax(&g_maxen, __float_as_int(s));
        atomicMax(&g_maxive, __float_as_int(inv));
    }
}

// ---------------- prepA: hs -> g_Axf fp32 (transposed) + int8 quant + row stats ----
__global__ void prepA_kernel(const float* __restrict__ hs) {
    __shared__ float tile[32][33];
    __shared__ float snorm[8][32];
    __shared__ float smax[8][32];
    __shared__ float sScale[32];
    int m0 = blockIdx.x * 32, b = m0 >> 10, p0 = m0 & 1023;
    int tx = threadIdx.x, ty = threadIdx.y;   // 32 x 8
    float nacc = 0.0f, macc = 0.0f;
    for (int cc = 0; cc < 8; cc++) {
        int c0 = cc * 32;
        __syncthreads();
        #pragma unroll
        for (int i = 0; i < 4; i++) {
            int c = c0 + ty + i * 8;
            float v = hs[((size_t)(b * 256 + c)) * 1024 + p0 + tx];
            tile[ty + i * 8][tx] = v;
            nacc = fmaf(v, v, nacc);
            macc = fmaxf(macc, fabsf(v));
        }
        __syncthreads();
        #pragma unroll
        for (int i = 0; i < 4; i++) {
            int row = ty + i * 8;
            g_Axf[(size_t)(m0 + row) * D + c0 + tx] = tile[tx][row];
        }
    }
    snorm[ty][tx] = nacc;
    smax[ty][tx] = macc;
    __syncthreads();
    if (ty == 0) {
        float tot = 0.0f, mx = 0.0f;
        #pragma unroll
        for (int j = 0; j < 8; j++) { tot += snorm[j][tx]; mx = fmaxf(mx, smax[j][tx]); }
        g_xn2[m0 + tx] = tot;
        float scale = 126.0f / mx;
        g_invsx[m0 + tx] = mx * (1.0f / 126.0f);
        sScale[tx] = scale;
    }
    __syncthreads();
    // fused quantization: FULL coverage — 32 rows x 32 segs (8B each), 4 per thread
    int tid = ty * 32 + tx;
    #pragma unroll
    for (int i = 0; i < 4; i++) {
        int t = tid + i * 256;
        int r = t >> 5, seg = t & 31;
        const float4* src = (const float4*)(g_Axf + (size_t)(m0 + r) * D + seg * 8);
        float4 a = src[0], c = src[1];
        float s = sScale[r];
        uint2 q;
        q.x = pack4i8(a.x, a.y, a.z, a.w, s);
        q.y = pack4i8(c.x, c.y, c.z, c.w, s);
        g_A8[(size_t)(m0 + r) * 32 + seg] = q;
    }
}

// ---------------- main GEMM (int8 mma.sync), CTA 128x128, 2-stage ------------------
#define SA_OFF(b) ((b) * 16384)
#define SB_OFF(b) (32768 + (b) * 16384)
#define SEN_OFF   65536
#define SIV_OFF   66048
#define SIX_OFF   66560
#define SPART_OFF 67072
#define SMEM_SZ   (1024 + 67072 + 4096)

__global__ void __launch_bounds__(256, 2)
gemm_kernel() {
    extern __shared__ char smem_raw[];
    char* base = (char*)(((uintptr_t)smem_raw + 1023) & ~(uintptr_t)1023);
    uint32_t sb = smem_u32(base);
    float* sEn = (float*)(base + SEN_OFF);
    float* sIv = (float*)(base + SIV_OFF);
    float* sIx = (float*)(base + SIX_OFF);
    u64* sPart = (u64*)(base + SPART_OFF);

    const int tid = threadIdx.x;
    const int lane = tid & 31, wid = tid >> 5;
    const int wm = wid & 3, wn = wid >> 2;
    const int ntile = blockIdx.x, mtile = blockIdx.y;
    const int m0 = mtile * 128, n0 = ntile * 128;

    if (tid < 128) {
        sEn[tid] = g_en2[n0 + tid];
        sIv[tid] = g_invse[n0 + tid];
        sIx[tid] = g_invsx[m0 + tid];
    }

    auto load_chunk = [&](int c, int bf) {
        #pragma unroll
        for (int it = 0; it < 4; it++) {
            int idx = tid + it * 256;
            int row = idx >> 3, kg = idx & 7;
            uint32_t soff = row * 128 + (((uint32_t)(kg ^ (row & 7))) << 4);
            cpasync16(sb + SA_OFF(bf) + soff,
                      (const char*)g_A8 + (size_t)(m0 + row) * 256 + c * 128 + kg * 16);
            cpasync16(sb + SB_OFF(bf) + soff,
                      (const char*)g_B8 + (size_t)(n0 + row) * 256 + c * 128 + kg * 16);
        }
        asm volatile("cp.async.commit_group;");
    };

    int acc[2][8][4];
    #pragma unroll
    for (int mt = 0; mt < 2; mt++)
        #pragma unroll
        for (int nt = 0; nt < 8; nt++)
            #pragma unroll
            for (int q = 0; q < 4; q++) acc[mt][nt][q] = 0;

    load_chunk(0, 0);

    for (int c = 0; c < 2; c++) {
        if (c + 1 < 2) {
            load_chunk(c + 1, (c + 1) & 1);
            asm volatile("cp.async.wait_group 1;" ::: "memory");
        } else {
            asm volatile("cp.async.wait_group 0;" ::: "memory");
        }
        __syncthreads();
        uint32_t ab = sb + SA_OFF(c & 1), bbse = sb + SB_OFF(c & 1);
        #pragma unroll
        for (int ks = 0; ks < 4; ks++) {
            uint32_t a[2][4], bb[8][2];
            uint32_t kg = ks * 2 + (lane >> 4);
            uint32_t kx = ((kg ^ (lane & 7)) << 4);
            #pragma unroll
            for (int mt = 0; mt < 2; mt++) {
                uint32_t row = wm * 32 + mt * 16 + (lane & 15);
                ldmx4(ab + row * 128 + kx, a[mt][0], a[mt][1], a[mt][2], a[mt][3]);
            }
            #pragma unroll
            for (int nt2 = 0; nt2 < 4; nt2++) {
                uint32_t row = wn * 64 + nt2 * 16 + (lane & 15);
                uint32_t r0, r1, r2, r3;
                ldmx4(bbse + row * 128 + kx, r0, r1, r2, r3);
                bb[nt2 * 2][0] = r0; bb[nt2 * 2][1] = r2;
                bb[nt2 * 2 + 1][0] = r1; bb[nt2 * 2 + 1][1] = r3;
            }
            #pragma unroll
            for (int mt = 0; mt < 2; mt++)
                #pragma unroll
                for (int nt = 0; nt < 8; nt++)
                    mma16832i(acc[mt][nt], a[mt], bb[nt]);
        }
        __syncthreads();
    }

    // epilogue: dist = en2 - 2*inv_sx*inv_se*dot_int ; per-row top-2 within tile
    #pragma unroll
    for (int mt = 0; mt < 2; mt++) {
        #pragma unroll
        for (int half = 0; half < 2; half++) {
            int rl = wm * 32 + mt * 16 + half * 8 + (lane >> 2);
            float m2ivx = -2.0f * sIx[rl];
            u64 t1 = ~0ull, t2 = ~0ull;
            #pragma unroll
            for (int nt = 0; nt < 8; nt++) {
                #pragma unroll
                for (int cc = 0; cc < 2; cc++) {
                    int col = wn * 64 + nt * 8 + (lane & 3) * 2 + cc;
                    float dist = fmaf((float)acc[mt][nt][half * 2 + cc],
                                      m2ivx * sIv[col], sEn[col]);
                    u64 pk = packdi(dist, n0 + col);
                    if (pk < t1) { t2 = t1; t1 = pk; }
                    else if (pk < t2) { t2 = pk; }
                }
            }
            #pragma unroll
            for (int dlt = 1; dlt <= 2; dlt <<= 1) {
                u64 o1 = __shfl_xor_sync(0xffffffffu, t1, dlt);
                u64 o2 = __shfl_xor_sync(0xffffffffu, t2, dlt);
                u64 n1 = min(t1, o1);
                u64 n2 = min(max(t1, o1), min(t2, o2));
                t1 = n1; t2 = n2;
            }
            if ((lane & 3) == 0) {
                sPart[rl * 4 + wn * 2] = t1;
                sPart[rl * 4 + wn * 2 + 1] = t2;
            }
        }
    }
    __syncthreads();
    if (tid < 128) {
        u64 p1 = ~0ull, p2 = ~0ull;
        #pragma unroll
        for (int w = 0; w < 2; w++) {
            u64 a1 = sPart[tid * 4 + w * 2], a2 = sPart[tid * 4 + w * 2 + 1];
            u64 n1 = min(p1, a1);
            u64 n2 = min(max(p1, a1), min(p2, a2));
            p1 = n1; p2 = n2;
        }
        // pack: [orderable d1 (32)] [idx (13)] [delta trunc-fp32, rounded down (19)]
        float d1 = unpackd(p1), d2 = unpackd(p2);
        uint32_t dq = __float_as_uint(fmaxf(d2 - d1, 0.0f)) >> 13;
        u64 packed = ((p1 >> 32) << 32)
                   | (((p1 & 0xFFFFFFFFull) & 0x1FFFull) << 19)
                   | (u64)(dq & 0x7FFFFu);
        g_part[(size_t)(m0 + tid) * 64 + ntile] = packed;
    }
}

// ---------------- merge_fast: warp/row (packed), fast path or enqueue tasks ---------
__global__ void merge_fast_kernel(float* __restrict__ out) {
    int wid = threadIdx.x >> 5, lane = threadIdx.x & 31;
    int row = blockIdx.x * 8 + wid;

    const ulonglong2* pp = (const ulonglong2*)(g_part + (size_t)row * 64);
    ulonglong2 ee = pp[lane];                  // tiles 2*lane, 2*lane+1

    u64 m = min(ee.x, ee.y);
    #pragma unroll
    for (int o = 16; o > 0; o >>= 1) m = min(m, __shfl_xor_sync(0xffffffffu, m, o));

    // int8 quantization pad: ~9 sigma of dist error
    float ivx = __ldg(&g_invsx[row]);
    float ive = __int_as_float(g_maxive);
    float pad = 5.2f * sqrtf(ivx * ivx * __int_as_float(g_maxen)
                             + ive * ive * __ldg(&g_xn2[row])) + 0.1f;
    float thr = unpackd(m) + pad;

    float d10 = unpackd(ee.x), d11 = unpackd(ee.y);
    float d20 = d10 + dec_delta(ee.x), d21 = d11 + dec_delta(ee.y);
    bool f0 = d20 <= thr, f1 = d21 <= thr;
    bool c0 = (!f0) && (d10 <= thr);
    bool c1 = (!f1) && (d11 <= thr);
    unsigned mf = __ballot_sync(0xffffffffu, f0 | f1);
    int nc = (int)c0 + (int)c1;
    #pragma unroll
    for (int o = 16; o > 0; o >>= 1) nc += __shfl_xor_sync(0xffffffffu, nc, o);

    if (mf == 0 && nc == 1) {
        if (lane == 0) {
            int k = (int)((m >> 19) & 0x1FFFu);
            g_idx[row] = k;
            out[IDX_OFF + row] = (float)k;
        }
        return;
    }

    if (lane == 0) {
        g_best[row] = ~0ull;
        g_rowq[atomicAdd(&g_rqn, 1)] = row;
    }
    int rsh = row << 13;
    if (c0) {
        int q = atomicAdd(&g_qn, 1);
        if (q < QCAP) g_queue[q] = rsh | (int)((ee.x >> 19) & 0x1FFFu);
    }
    if (c1) {
        int q = atomicAdd(&g_qn, 1);
        if (q < QCAP) g_queue[q] = rsh | (int)((ee.y >> 19) & 0x1FFFu);
    }
    if (f0) {
        int q = atomicAdd(&g_qn, 128);
        int k0 = (lane * 2) * 128;
        for (int i = 0; i < 128 && q + i < QCAP; i++) g_queue[q + i] = rsh | (k0 + i);
    }
    if (f1) {
        int q = atomicAdd(&g_qn, 128);
        int k0 = (lane * 2 + 1) * 128;
        for (int i = 0; i < 128 && q + i < QCAP; i++) g_queue[q + i] = rsh | (k0 + i);
    }
}

// ---------------- merge_slow: one warp per candidate task ---------------------------
__global__ void __launch_bounds__(256, 8)
merge_slow_kernel(const float* __restrict__ E) {
    int nt = g_qn;
    if (nt > QCAP) nt = QCAP;
    int lane = threadIdx.x & 31;
    int gw = (blockIdx.x * 256 + threadIdx.x) >> 5;
    int nwarp = (gridDim.x * 256) >> 5;

    for (int t = gw; t < nt; t += nwarp) {
        int task = g_queue[t];
        int row = task >> 13, k = task & 0x1FFF;
        const float* xr = g_Axf + (size_t)row * D;
        const float* ek = E + (size_t)k * D;
        float s = 0.0f;
        #pragma unroll
        for (int j = 0; j < 8; j++)
            s = fmaf(__ldg(xr + lane + j * 32), __ldg(ek + lane + j * 32), s);
        #pragma unroll
        for (int o = 16; o > 0; o >>= 1) s += __shfl_xor_sync(0xffffffffu, s, o);
        if (lane == 0) {
            float dist = fmaf(-2.0f, s, __ldg(&g_en2[k]));
            atomicMin(&g_best[row], packdi(dist, k));
        }
    }
}

// ---------------- merge_fin: finalize queued rows ------------------------------------
__global__ void merge_fin_kernel(float* __restrict__ out) {
    int n = g_rqn;
    for (int i = blockIdx.x * 256 + threadIdx.x; i < n; i += gridDim.x * 256) {
        int row = g_rowq[i];
        int k = (int)(g_best[row] & 0xFFFFFFFFu);
        g_idx[row] = k;
        out[IDX_OFF + row] = (float)k;
    }
}

// ---------------- final: 512 CTAs x 32 rows, smem-staged E gather -------------------
__global__ void __launch_bounds__(256, 4)
final_kernel(const float* __restrict__ hs, const float* __restrict__ E,
             float* __restrict__ out) {
    __shared__ int sIdx[32];
    __shared__ float sE[32 * 257];
    __shared__ float sRed[8];
    int tid = threadIdx.x, lane = tid & 31, wid = tid >> 5;
    int row0 = blockIdx.x * 32;
    int b = row0 >> 10, p0 = row0 & 1023;
    size_t xbase = (size_t)b * 256 * 1024 + p0;

    if (tid < 32) sIdx[tid] = g_idx[row0 + tid];
    __syncthreads();

    // stage 32 gathered E rows, coalesced reads, conflict-free smem (stride 257)
    #pragma unroll
    for (int j = 0; j < 4; j++) {
        int r = wid * 4 + j;
        const float* ek = E + (size_t)sIdx[r] * D;
        #pragma unroll
        for (int q = 0; q < 8; q++)
            sE[r * 257 + q * 32 + lane] = __ldg(ek + q * 32 + lane);
    }
    __syncthreads();

    // lanes = rows (coalesced hs read / out write); warps cover c space
    float lsum = 0.0f;
    const float* sEr = sE + lane * 257;
    #pragma unroll 4
    for (int i = 0; i < 32; i++) {
        int c = wid + 8 * i;
        size_t ad = xbase + (size_t)c * 1024 + lane;
        float xv = hs[ad];
        float ev = sEr[c];
        out[ad] = ev;
        float d = ev - xv;
        lsum = fmaf(d, d, lsum);
    }
    #pragma unroll
    for (int o = 16; o > 0; o >>= 1) lsum += __shfl_xor_sync(0xffffffffu, lsum, o);
    if (lane == 0) sRed[wid] = lsum;
    __syncthreads();
    if (tid == 0) {
        float tot = 0.0f;
        #pragma unroll
        for (int w = 0; w < 8; w++) tot += sRed[w];
        atomicAdd(out + LOSS_OFF, tot * (1.25f / 4194304.0f));
    }
}

extern "C" void kernel_launch(void* const* d_in, const int* in_sizes, int n_in,
                              void* d_out, int out_size) {
    const float* hs = (const float*)d_in[0];
    const float* E  = (const float*)d_in[1];
    float* out = (float*)d_out;

    cudaFuncSetAttribute(gemm_kernel,
                         cudaFuncAttributeMaxDynamicSharedMemorySize, SMEM_SZ);

    prepE_kernel<<<KC / 8, 256>>>(E, out);
    prepA_kernel<<<N_ROWS / 32, dim3(32, 8)>>>(hs);
    gemm_kernel<<<dim3(KC / 128, N_ROWS / 128), 256, SMEM_SZ>>>();
    merge_fast_kernel<<<N_ROWS / 8, 256>>>(out);
    merge_slow_kernel<<<592, 256>>>(E);
    merge_fin_kernel<<<32, 256>>>(out);
    final_kernel<<<N_ROWS / 32, 256>>>(hs, E, out);
}